// round 5
// baseline (speedup 1.0000x reference)
#include <cuda_runtime.h>

// Problem constants (fixed by setup_inputs)
#define Nn 4
#define Cc 19
#define Hh 128
#define Ww 128
#define HIN 512
#define WIN 512

#define Rr 5                    // kernels_radius (fixed by setup_inputs)
#define Dd 11                   // 2*Rr+1
#define CPAD 20                 // 19 channels padded to 20 floats (80B, 16B-aligned)
#define ROWS 4                  // output rows per block
#define NTHREADS 256            // 2 vertical pairs x 128 cols
#define SROWS (Dd+ROWS-1)       // 14 halo rows staged
#define NBLOCKS (Nn*Hh/ROWS)    // 128

// Scratch (no allocations allowed)
__device__ float g_rgb[Nn*3*Hh*Ww];   // downsampled rgb, already divided by sigma=0.1
__device__ float g_part[NBLOCKS];

// Packed f32x2 FMA (Blackwell): acc = a*b + acc, two floats per op
#define FMA2(acc, a, b) \
    asm("fma.rn.f32x2 %0, %1, %2, %0;" : "+l"(acc) : "l"(a), "l"(b))

// Pack one float into both halves of a u64 (f32x2 broadcast)
#define PACK2(dst, f) \
    asm("mov.b64 %0, {%1, %1};" : "=l"(dst) : "r"(__float_as_uint(f)))

__device__ __forceinline__ float hadd2(unsigned long long v) {
    unsigned int lo, hi;
    asm("mov.b64 {%0,%1}, %2;" : "=r"(lo), "=r"(hi) : "l"(v));
    return __uint_as_float(lo) + __uint_as_float(hi);
}

// ---------------------------------------------------------------------------
// 1) 4x4 block-mean downsample of sample (4,3,512,512) -> (4,3,128,128), /0.1
// ---------------------------------------------------------------------------
__global__ void k_downsample(const float* __restrict__ sample) {
    int idx = blockIdx.x * blockDim.x + threadIdx.x;
    if (idx >= Nn*3*Hh*Ww) return;
    int x  = idx & (Ww-1);
    int t  = idx >> 7;
    int y  = t & (Hh-1);
    int nc = t >> 7;              // n*3 + c
    const float* src = sample + ((size_t)nc*HIN + (size_t)y*4)*WIN + (size_t)x*4;
    float s = 0.f;
#pragma unroll
    for (int i = 0; i < 4; i++)
#pragma unroll
        for (int j = 0; j < 4; j++) s += src[i*WIN + j];
    g_rgb[idx] = (s * (1.0f/16.0f)) / 0.1f;
}

// ---------------------------------------------------------------------------
// 2) Main fused kernel: block = 4 output rows; thread = vertical center pair.
//    Separable xy-Gaussian; validity masks folded into the Gaussian factors.
// ---------------------------------------------------------------------------
extern __shared__ float smem[];

__global__ __launch_bounds__(NTHREADS) void k_main(
    const float* __restrict__ yhat,
    const float* __restrict__ corr)
{
    float* sh_y   = smem;                        // [SROWS][Ww][CPAD]
    float* sh_rgb = sh_y + SROWS*Ww*CPAD;        // [SROWS][Ww][4]
    float* sh_red = sh_rgb + SROWS*Ww*4;         // [NTHREADS]

    const int tid = threadIdx.x;
    const int x   = tid & (Ww-1);
    const int pr  = tid >> 7;                    // 0..1 (pair index)
    const int blk = blockIdx.x;
    const int n     = blk >> 5;                  // blk / 32
    const int ybase = (blk & 31) * ROWS;
    const int ya    = ybase + 2*pr;              // first center
    const int yb    = ya + 1;                    // second center

    // Stage y_hat halo rows (pixel-major, padded channel dim)
#pragma unroll 1
    for (int p = pr; p < SROWS*Cc; p += 2) {
        int row = p / Cc, c = p - row*Cc;
        int yy = ybase - Rr + row;
        float v = 0.f;
        if (yy >= 0 && yy < Hh)
            v = yhat[(((size_t)n*Cc + c)*Hh + yy)*Ww + x];
        sh_y[(row*Ww + x)*CPAD + c] = v;
    }
    for (int p = pr; p < SROWS; p += 2)
        sh_y[(p*Ww + x)*CPAD + (CPAD-1)] = 0.f;   // pad lane clean
    for (int p = pr; p < SROWS*3; p += 2) {
        int row = p / 3, c = p - row*3;
        int yy = ybase - Rr + row;
        float v = 0.f;
        if (yy >= 0 && yy < Hh)
            v = g_rgb[((n*3 + c)*Hh + yy)*Ww + x];
        sh_rgb[(row*Ww + x)*4 + c] = v;
    }
    __syncthreads();

    // Center feature vectors, packed as f32x2 pairs (10 u64 each)
    unsigned long long ca[10], cb[10];
    {
        const ulonglong2* pa = (const ulonglong2*)&sh_y[(((ya-(ybase-Rr))*Ww) + x)*CPAD];
        const ulonglong2* pb = (const ulonglong2*)&sh_y[(((yb-(ybase-Rr))*Ww) + x)*CPAD];
#pragma unroll
        for (int i = 0; i < 5; i++) {
            ulonglong2 ta = pa[i], tb = pb[i];
            ca[2*i] = ta.x; ca[2*i+1] = ta.y;
            cb[2*i] = tb.x; cb[2*i+1] = tb.y;
        }
    }
    float4 cra = *(const float4*)&sh_rgb[(((ya-(ybase-Rr))*Ww) + x)*4];
    float4 crb = *(const float4*)&sh_rgb[(((yb-(ybase-Rr))*Ww) + x)*4];

    // Column factors with validity folded in:
    //   wcolf[j] = (x+j-Rr in bounds) * exp(-(j-Rr)^2/72)
    // wcolf[Rr] = 1.0f exactly (in-bounds, __expf(0)=1) -> center cancellation exact.
    int   xxc[Dd];
    float wcolf[Dd];
#pragma unroll
    for (int j = 0; j < Dd; j++) {
        int xx = x + j - Rr;
        xxc[j] = min(max(xx, 0), Ww-1);
        float g = __expf((float)((j-Rr)*(j-Rr)) * (-1.0f/72.0f));
        wcolf[j] = (xx >= 0 && xx < Ww) ? g : 0.f;
    }

    // OOB tap value per center: e_xy(ctr)*(0.9*e_rgb(ctr)+0.1)  (y_unf = 0 there)
    const float fx  = (float)x  * (1.0f/6.0f);
    const float fya = (float)ya * (1.0f/6.0f);
    const float fyb = (float)yb * (1.0f/6.0f);
    const float koob_a = __expf(-0.5f*(fx*fx + fya*fya))
                       * (0.9f*__expf(-0.5f*(cra.x*cra.x + cra.y*cra.y + cra.z*cra.z)) + 0.1f);
    const float koob_b = __expf(-0.5f*(fx*fx + fyb*fyb))
                       * (0.9f*__expf(-0.5f*(crb.x*crb.x + crb.y*crb.y + crb.z*crb.z)) + 0.1f);

    const int x0 = max(x - Rr, 0), x1 = min(x + Rr, Ww-1);
    const int nx = x1 - x0 + 1;
    const int nin_a = (min(ya+Rr, Hh-1) - max(ya-Rr, 0) + 1) * nx;
    const int nin_b = (min(yb+Rr, Hh-1) - max(yb-Rr, 0) + 1) * nx;

    float ksum_a = (float)(Dd*Dd - nin_a) * koob_a;
    float ksum_b = (float)(Dd*Dd - nin_b) * koob_b;
    unsigned long long psa = 0ull, psb = 0ull;   // packed psum accumulators

    // Center self-dots via identical FMA2 sequence (bitwise == loop's center acc)
    float dot_ca, dot_cb;
    {
        unsigned long long sa = 0ull, sb = 0ull;
#pragma unroll
        for (int i = 0; i < 10; i++) { FMA2(sa, ca[i], ca[i]); FMA2(sb, cb[i], cb[i]); }
        dot_ca = hadd2(sa); dot_cb = hadd2(sb);
    }

    const int yu0 = max(ya - Rr, 0);
    const int yu1 = min(yb + Rr, Hh-1);

#pragma unroll 1
    for (int yy = yu0; yy <= yu1; yy++) {
        const int row = yy - (ybase - Rr);
        const float* rowy = sh_y   + row*Ww*CPAD;
        const float* rowg = sh_rgb + row*Ww*4;
        const int dya = yy - ya;
        const int dyb = yy - yb;
        // Row factor with row-validity folded in (invalid rows -> 0 -> taps vanish)
        const float rfa = (yy <= ya + Rr) ? __expf((float)(dya*dya) * (-1.0f/72.0f)) : 0.f;
        const float rfb = (yy >= yb - Rr) ? __expf((float)(dyb*dyb) * (-1.0f/72.0f)) : 0.f;

#pragma unroll
        for (int j = 0; j < Dd; j++) {
            const int xc = xxc[j];
            float4 ng = *(const float4*)&rowg[xc*4];
            float da0 = ng.x - cra.x, da1 = ng.y - cra.y, da2 = ng.z - cra.z;
            float db0 = ng.x - crb.x, db1 = ng.y - crb.y, db2 = ng.z - crb.z;
            float ta = 0.9f*__expf(-0.5f*(da0*da0 + da1*da1 + da2*da2)) + 0.1f;
            float tb = 0.9f*__expf(-0.5f*(db0*db0 + db1*db1 + db2*db2)) + 0.1f;
            float k_a = (rfa * wcolf[j]) * ta;   // center: 1*1*1 = 1.0f exactly
            float k_b = (rfb * wcolf[j]) * tb;

            const ulonglong2* nb = (const ulonglong2*)(rowy + xc*CPAD);
            unsigned long long acc_a = 0ull, acc_b = 0ull;
#pragma unroll
            for (int i = 0; i < 5; i++) {
                ulonglong2 v = nb[i];
                FMA2(acc_a, v.x, ca[2*i]);   FMA2(acc_a, v.y, ca[2*i+1]);
                FMA2(acc_b, v.x, cb[2*i]);   FMA2(acc_b, v.y, cb[2*i+1]);
            }
            unsigned long long kk_a, kk_b;
            PACK2(kk_a, k_a);
            PACK2(kk_b, k_b);
            FMA2(psa, kk_a, acc_a);          // psum pair += k * dot-halves
            FMA2(psb, kk_b, acc_b);
            ksum_a += k_a;
            ksum_b += k_b;
        }
    }
    // Remove center taps (k == 1.0 exactly; packed center dot == sa/sb bitwise)
    float psum_a = hadd2(psa) - dot_ca;
    float psum_b = hadd2(psb) - dot_cb;
    ksum_a -= 1.0f;
    ksum_b -= 1.0f;

    const float corr_a = corr[((size_t)n*Hh + ya)*Ww + x];
    const float corr_b = corr[((size_t)n*Hh + yb)*Ww + x];
    float part = (ksum_a - psum_a*corr_a) + (ksum_b - psum_b*corr_b);

    // Deterministic block reduction
    sh_red[tid] = part;
    __syncthreads();
    for (int s = NTHREADS/2; s > 0; s >>= 1) {
        if (tid < s) sh_red[tid] += sh_red[tid + s];
        __syncthreads();
    }
    if (tid == 0) g_part[blk] = sh_red[0];
}

// ---------------------------------------------------------------------------
// 3) Final reduction: sum 128 block partials, divide by N*H*W
// ---------------------------------------------------------------------------
__global__ void k_final(float* __restrict__ out) {
    __shared__ float s[128];
    float v = 0.f;
    for (int i = threadIdx.x; i < NBLOCKS; i += 128) v += g_part[i];
    s[threadIdx.x] = v;
    __syncthreads();
    for (int t = 64; t > 0; t >>= 1) {
        if (threadIdx.x < t) s[threadIdx.x] += s[threadIdx.x + t];
        __syncthreads();
    }
    if (threadIdx.x == 0) out[0] = s[0] * (1.0f / (float)(Nn*Hh*Ww));
}

// ---------------------------------------------------------------------------
extern "C" void kernel_launch(void* const* d_in, const int* in_sizes, int n_in,
                              void* d_out, int out_size)
{
    const float* yhat   = (const float*)d_in[0];
    const float* sample = (const float*)d_in[1];
    const float* corr   = (const float*)d_in[2];
    float* out = (float*)d_out;
    (void)in_sizes; (void)n_in; (void)out_size;

    k_downsample<<<(Nn*3*Hh*Ww + 255)/256, 256>>>(sample);

    size_t smem_bytes = (size_t)(SROWS*Ww*CPAD + SROWS*Ww*4 + NTHREADS)
                        * sizeof(float);   // ~169 KB
    cudaFuncSetAttribute(k_main, cudaFuncAttributeMaxDynamicSharedMemorySize,
                         (int)smem_bytes);
    k_main<<<NBLOCKS, NTHREADS, smem_bytes>>>(yhat, corr);

    k_final<<<1, 128>>>(out);
}

// round 16
// speedup vs baseline: 1.7152x; 1.7152x over previous
#include <cuda_runtime.h>

// Problem constants (fixed by setup_inputs)
#define Nn 4
#define Cc 19
#define Hh 128
#define Ww 128
#define HIN 512
#define WIN 512

#define Rr 5                    // kernels_radius (fixed by setup_inputs)
#define Dd 11                   // 2*Rr+1
#define CPAD 20                 // 19 channels padded to 20 floats (80B, 16B-aligned)
#define ROWS 4                  // output rows per block
#define NTHREADS 512            // 2 pairs x 2 column-parities x 128 cols
#define NWARPS (NTHREADS/32)
#define SROWS (Dd+ROWS-1)       // 14 halo rows staged
#define NBLOCKS (Nn*Hh/ROWS)    // 128

// Scratch (no allocations allowed)
__device__ float g_rgb[Nn*3*Hh*Ww];   // downsampled rgb, already divided by sigma=0.1
__device__ float g_part[NBLOCKS];
__device__ unsigned int g_count = 0;  // last-block ticket (reset by last block)

// Packed f32x2 ops (Blackwell)
#define FMA2(acc, a, b) \
    asm("fma.rn.f32x2 %0, %1, %2, %0;" : "+l"(acc) : "l"(a), "l"(b))
#define ADD2(dst, a, b) \
    asm("add.rn.f32x2 %0, %1, %2;" : "=l"(dst) : "l"(a), "l"(b))
#define PACK2(dst, f) \
    asm("mov.b64 %0, {%1, %1};" : "=l"(dst) : "r"(__float_as_uint(f)))

__device__ __forceinline__ float hadd2(unsigned long long v) {
    unsigned int lo, hi;
    asm("mov.b64 {%0,%1}, %2;" : "=r"(lo), "=r"(hi) : "l"(v));
    return __uint_as_float(lo) + __uint_as_float(hi);
}

// ---------------------------------------------------------------------------
// 1) 4x4 block-mean downsample of sample (4,3,512,512) -> (4,3,128,128), /0.1
//    Two adjacent-x outputs per thread -> 8 independent LDG.128 in flight
//    (R5 profile showed this kernel MLP/latency-starved at MLP=4).
// ---------------------------------------------------------------------------
__global__ void k_downsample(const float* __restrict__ sample) {
    int o = (blockIdx.x * blockDim.x + threadIdx.x) * 2;
    if (o >= Nn*3*Hh*Ww) return;
    int x  = o & (Ww-1);          // even; x+1 in same row (Ww is even)
    int t  = o >> 7;
    int y  = t & (Hh-1);
    int nc = t >> 7;              // n*3 + c
    const float4* src = (const float4*)(sample + ((size_t)nc*HIN + (size_t)y*4)*WIN) + x;
    float s0 = 0.f, s1 = 0.f;
#pragma unroll
    for (int i = 0; i < 4; i++) {
        float4 v0 = src[i*(WIN/4)];
        float4 v1 = src[i*(WIN/4) + 1];
        s0 += (v0.x + v0.y) + (v0.z + v0.w);
        s1 += (v1.x + v1.y) + (v1.z + v1.w);
    }
    g_rgb[o]     = (s0 * (1.0f/16.0f)) / 0.1f;
    g_rgb[o + 1] = (s1 * (1.0f/16.0f)) / 0.1f;
}

// ---------------------------------------------------------------------------
// Tap work for one column-parity half of one vertical center pair.
// HALF = starting column parity (0: j=0,2,..,10 [6 cols]; 1: j=1,3,..,9 [5 cols])
// HALF==1 owns the center column (j=Rr=5): performs exact center-tap removal.
// HALF==0 carries the closed-form OOB contribution.
// ---------------------------------------------------------------------------
template<int HALF, int NJ>
__device__ __forceinline__ float tap_work(
    const float* __restrict__ sh_y, const float* __restrict__ sh_rgb,
    int x, int ya, int yb, int ybase,
    const unsigned long long* ca, const unsigned long long* cb,
    float4 cra, float4 crb, float corr_a, float corr_b)
{
    // Column setup (validity folded into the column Gaussian)
    int   xxc[NJ];
    float wcolf[NJ];
#pragma unroll
    for (int jj = 0; jj < NJ; jj++) {
        int j  = HALF + 2*jj;
        int xx = x + j - Rr;
        xxc[jj] = min(max(xx, 0), Ww-1);
        float g = __expf((float)((j-Rr)*(j-Rr)) * (-1.0f/72.0f));
        wcolf[jj] = (xx >= 0 && xx < Ww) ? g : 0.f;
    }

    float ksum_a, ksum_b;
    if (HALF == 0) {
        // OOB taps: value e_xy(ctr)*(0.9*e_rgb(ctr)+0.1), y_unf = 0 there
        const float fx  = (float)x  * (1.0f/6.0f);
        const float fya = (float)ya * (1.0f/6.0f);
        const float fyb = (float)yb * (1.0f/6.0f);
        const float koob_a = __expf(-0.5f*(fx*fx + fya*fya))
            * (0.9f*__expf(-0.5f*(cra.x*cra.x + cra.y*cra.y + cra.z*cra.z)) + 0.1f);
        const float koob_b = __expf(-0.5f*(fx*fx + fyb*fyb))
            * (0.9f*__expf(-0.5f*(crb.x*crb.x + crb.y*crb.y + crb.z*crb.z)) + 0.1f);
        const int x0 = max(x - Rr, 0), x1 = min(x + Rr, Ww-1);
        const int nx = x1 - x0 + 1;
        const int nin_a = (min(ya+Rr, Hh-1) - max(ya-Rr, 0) + 1) * nx;
        const int nin_b = (min(yb+Rr, Hh-1) - max(yb-Rr, 0) + 1) * nx;
        ksum_a = (float)(Dd*Dd - nin_a) * koob_a;
        ksum_b = (float)(Dd*Dd - nin_b) * koob_b;
    } else {
        ksum_a = 0.f;
        ksum_b = 0.f;
    }

    // Center self-dots via the IDENTICAL split-chain FMA2 sequence
    float dot_ca = 0.f, dot_cb = 0.f;
    if (HALF == 1) {
        unsigned long long sa0 = 0ull, sa1 = 0ull, sb0 = 0ull, sb1 = 0ull;
#pragma unroll
        for (int i = 0; i < 5; i++) {
            FMA2(sa0, ca[2*i],   ca[2*i]);   FMA2(sa1, ca[2*i+1], ca[2*i+1]);
            FMA2(sb0, cb[2*i],   cb[2*i]);   FMA2(sb1, cb[2*i+1], cb[2*i+1]);
        }
        unsigned long long sa, sb;
        ADD2(sa, sa0, sa1); ADD2(sb, sb0, sb1);
        dot_ca = hadd2(sa); dot_cb = hadd2(sb);
    }

    unsigned long long psa = 0ull, psb = 0ull;   // packed psum accumulators

    const int yu0 = max(ya - Rr, 0);
    const int yu1 = min(yb + Rr, Hh-1);

#pragma unroll 1
    for (int yy = yu0; yy <= yu1; yy++) {
        const int row = yy - (ybase - Rr);
        const float* rowy = sh_y   + row*Ww*CPAD;
        const float* rowg = sh_rgb + row*Ww*4;
        const int dya = yy - ya;
        const int dyb = yy - yb;
        // Row factor with row-validity folded in (invalid rows -> 0 -> taps vanish)
        const float rfa = (yy <= ya + Rr) ? __expf((float)(dya*dya) * (-1.0f/72.0f)) : 0.f;
        const float rfb = (yy >= yb - Rr) ? __expf((float)(dyb*dyb) * (-1.0f/72.0f)) : 0.f;

#pragma unroll
        for (int jj = 0; jj < NJ; jj++) {
            const int xc = xxc[jj];
            float4 ng = *(const float4*)&rowg[xc*4];
            float da0 = ng.x - cra.x, da1 = ng.y - cra.y, da2 = ng.z - cra.z;
            float db0 = ng.x - crb.x, db1 = ng.y - crb.y, db2 = ng.z - crb.z;
            float ta = 0.9f*__expf(-0.5f*(da0*da0 + da1*da1 + da2*da2)) + 0.1f;
            float tb = 0.9f*__expf(-0.5f*(db0*db0 + db1*db1 + db2*db2)) + 0.1f;
            float k_a = (rfa * wcolf[jj]) * ta;   // center: 1*1*1 = 1.0f exactly
            float k_b = (rfb * wcolf[jj]) * tb;

            const ulonglong2* nb = (const ulonglong2*)(rowy + xc*CPAD);
            // Split dot chains: two 5-deep FMA2 chains per center (2x ILP)
            unsigned long long a0 = 0ull, a1 = 0ull, b0 = 0ull, b1 = 0ull;
#pragma unroll
            for (int i = 0; i < 5; i++) {
                ulonglong2 v = nb[i];
                FMA2(a0, v.x, ca[2*i]);   FMA2(a1, v.y, ca[2*i+1]);
                FMA2(b0, v.x, cb[2*i]);   FMA2(b1, v.y, cb[2*i+1]);
            }
            unsigned long long acc_a, acc_b;
            ADD2(acc_a, a0, a1);
            ADD2(acc_b, b0, b1);
            unsigned long long kk_a, kk_b;
            PACK2(kk_a, k_a);
            PACK2(kk_b, k_b);
            FMA2(psa, kk_a, acc_a);          // psum pair += k * dot-halves
            FMA2(psb, kk_b, acc_b);
            ksum_a += k_a;
            ksum_b += k_b;
        }
    }

    float psum_a = hadd2(psa);
    float psum_b = hadd2(psb);
    if (HALF == 1) {  // remove center taps (k == 1.0 exactly; dots cancel bitwise)
        psum_a -= dot_ca;  psum_b -= dot_cb;
        ksum_a -= 1.0f;    ksum_b -= 1.0f;
    }
    return (ksum_a - psum_a*corr_a) + (ksum_b - psum_b*corr_b);
}

// ---------------------------------------------------------------------------
// 2) Main fused kernel: block = 4 output rows; thread = (vertical pair, parity).
//    Last finishing block performs the global reduction (fused k_final).
// ---------------------------------------------------------------------------
extern __shared__ float smem[];

__global__ __launch_bounds__(NTHREADS) void k_main(
    const float* __restrict__ yhat,
    const float* __restrict__ corr,
    float* __restrict__ out)
{
    float* sh_y   = smem;                        // [SROWS][Ww][CPAD]
    float* sh_rgb = sh_y + SROWS*Ww*CPAD;        // [SROWS][Ww][4]
    float* sh_red = sh_rgb + SROWS*Ww*4;         // [NWARPS]

    const int tid  = threadIdx.x;
    const int x    = tid & (Ww-1);
    const int lane = tid >> 7;                   // 0..3
    const int half = lane & 1;                   // column parity
    const int pr   = lane >> 1;                  // 0..1 vertical pair
    const int blk = blockIdx.x;
    const int n     = blk >> 5;                  // blk / 32
    const int ybase = (blk & 31) * ROWS;
    const int ya    = ybase + 2*pr;              // first center
    const int yb    = ya + 1;                    // second center

    // Stage y_hat halo rows (pixel-major, padded channel dim); 4-way strided.
    // Incremental (row, c) tracking avoids a divide; unroll 4 batches 4
    // independent LDGs ahead of their STSs (raises staging-phase MLP ~4x).
    {
        int row = 0, c = lane;                   // lane < 4 <= Cc
#pragma unroll 4
        for (int p = lane; p < SROWS*Cc; p += 4) {
            int yy = ybase - Rr + row;
            float v = 0.f;
            if (yy >= 0 && yy < Hh)
                v = yhat[(((size_t)n*Cc + c)*Hh + yy)*Ww + x];
            sh_y[(row*Ww + x)*CPAD + c] = v;
            c += 4;
            if (c >= Cc) { c -= Cc; row++; }
        }
    }
    for (int p = lane; p < SROWS; p += 4)
        sh_y[(p*Ww + x)*CPAD + (CPAD-1)] = 0.f;   // pad lane clean
#pragma unroll
    for (int p = lane; p < SROWS*3; p += 4) {
        int row = p / 3, c = p - row*3;
        int yy = ybase - Rr + row;
        float v = 0.f;
        if (yy >= 0 && yy < Hh)
            v = g_rgb[((n*3 + c)*Hh + yy)*Ww + x];
        sh_rgb[(row*Ww + x)*4 + c] = v;
    }
    __syncthreads();

    // Center feature vectors, packed as f32x2 pairs (10 u64 each)
    unsigned long long ca[10], cb[10];
    {
        const ulonglong2* pa = (const ulonglong2*)&sh_y[(((ya-(ybase-Rr))*Ww) + x)*CPAD];
        const ulonglong2* pb = (const ulonglong2*)&sh_y[(((yb-(ybase-Rr))*Ww) + x)*CPAD];
#pragma unroll
        for (int i = 0; i < 5; i++) {
            ulonglong2 ta = pa[i], tb = pb[i];
            ca[2*i] = ta.x; ca[2*i+1] = ta.y;
            cb[2*i] = tb.x; cb[2*i+1] = tb.y;
        }
    }
    float4 cra = *(const float4*)&sh_rgb[(((ya-(ybase-Rr))*Ww) + x)*4];
    float4 crb = *(const float4*)&sh_rgb[(((yb-(ybase-Rr))*Ww) + x)*4];

    const float corr_a = corr[((size_t)n*Hh + ya)*Ww + x];
    const float corr_b = corr[((size_t)n*Hh + yb)*Ww + x];

    // Warp-uniform parity branch (tid>>7 uniform within a warp)
    float part;
    if (half == 0)
        part = tap_work<0, 6>(sh_y, sh_rgb, x, ya, yb, ybase, ca, cb, cra, crb, corr_a, corr_b);
    else
        part = tap_work<1, 5>(sh_y, sh_rgb, x, ya, yb, ybase, ca, cb, cra, crb, corr_a, corr_b);

    // Deterministic reduction: xor-butterfly (bitwise-identical on all lanes)
#pragma unroll
    for (int m = 16; m > 0; m >>= 1)
        part += __shfl_xor_sync(0xFFFFFFFFu, part, m);
    if ((tid & 31) == 0) sh_red[tid >> 5] = part;
    __syncthreads();

    if (tid < 32) {
        float v = (tid < NWARPS) ? sh_red[tid] : 0.f;
#pragma unroll
        for (int m = 16; m > 0; m >>= 1)
            v += __shfl_xor_sync(0xFFFFFFFFu, v, m);

        unsigned int last = 0u;
        if (tid == 0) {
            g_part[blk] = v;
            __threadfence();                               // release g_part write
            last = (atomicAdd(&g_count, 1u) == NBLOCKS - 1u) ? 1u : 0u;
        }
        last = __shfl_sync(0xFFFFFFFFu, last, 0);
        if (last) {
            __threadfence();                               // acquire other blocks' writes
            // Lane i sums g_part[4i..4i+3] in fixed order, then butterfly:
            // fixed combining structure -> deterministic.
            float s = 0.f;
#pragma unroll
            for (int i = 0; i < 4; i++) s += g_part[tid*4 + i];
#pragma unroll
            for (int m = 16; m > 0; m >>= 1)
                s += __shfl_xor_sync(0xFFFFFFFFu, s, m);
            if (tid == 0) {
                out[0] = s * (1.0f / (float)(Nn*Hh*Ww));
                g_count = 0;                               // reset for next replay
            }
        }
    }
}

// ---------------------------------------------------------------------------
extern "C" void kernel_launch(void* const* d_in, const int* in_sizes, int n_in,
                              void* d_out, int out_size)
{
    const float* yhat   = (const float*)d_in[0];
    const float* sample = (const float*)d_in[1];
    const float* corr   = (const float*)d_in[2];
    float* out = (float*)d_out;
    (void)in_sizes; (void)n_in; (void)out_size;

    k_downsample<<<(Nn*3*Hh*Ww/2 + 255)/256, 256>>>(sample);

    size_t smem_bytes = (size_t)(SROWS*Ww*CPAD + SROWS*Ww*4 + NWARPS)
                        * sizeof(float);   // ~168.6 KB
    cudaFuncSetAttribute(k_main, cudaFuncAttributeMaxDynamicSharedMemorySize,
                         (int)smem_bytes);
    k_main<<<NBLOCKS, NTHREADS, smem_bytes>>>(yhat, corr, out);
}